// round 3
// baseline (speedup 1.0000x reference)
#include <cuda_runtime.h>
#include <cuda_bf16.h>

// Problem constants
#define BB 2
#define SS 2048
#define HH 12
#define DK 64
#define DM 768
#define MROWS (BB * SS)        // 4096
#define ELEMS (BB * SS * DM)   // 3,145,728

// Scratch (no allocation allowed -> __device__ globals)
__device__ float g_q[ELEMS];
__device__ float g_k[ELEMS];
__device__ float g_v[ELEMS];
__device__ float g_ctx[ELEMS];

// ---------------------------------------------------------------------------
// Tiled SGEMM with bias:  C[M,N] = A[M,K] @ W[N,K]^T + bias[N]
// 64x64 tile, BK=16, 256 threads, 4x4 micro-tile per thread.
// ---------------------------------------------------------------------------
#define TILE 64
#define BK 16

__global__ __launch_bounds__(256) void sgemm_bias_kernel(
    const float* __restrict__ A,
    const float* __restrict__ W,
    const float* __restrict__ bias,
    float* __restrict__ C,
    int M, int N, int K)
{
    __shared__ float As[BK][TILE];   // [k][m]
    __shared__ float Ws[BK][TILE];   // [k][n]

    const int tid = threadIdx.x;
    const int tx = tid & 15;         // 0..15 -> n micro
    const int ty = tid >> 4;         // 0..15 -> m micro
    const int bm = blockIdx.y * TILE;
    const int bn = blockIdx.x * TILE;

    const int lr  = tid >> 2;        // 0..63 row within tile
    const int lcb = (tid & 3) * 4;   // 0,4,8,12 k-offset

    float acc[4][4];
#pragma unroll
    for (int i = 0; i < 4; i++)
#pragma unroll
        for (int j = 0; j < 4; j++) acc[i][j] = 0.0f;

    for (int k0 = 0; k0 < K; k0 += BK) {
        float4 av = *(const float4*)&A[(size_t)(bm + lr) * K + k0 + lcb];
        float4 wv = *(const float4*)&W[(size_t)(bn + lr) * K + k0 + lcb];
        As[lcb + 0][lr] = av.x; As[lcb + 1][lr] = av.y;
        As[lcb + 2][lr] = av.z; As[lcb + 3][lr] = av.w;
        Ws[lcb + 0][lr] = wv.x; Ws[lcb + 1][lr] = wv.y;
        Ws[lcb + 2][lr] = wv.z; Ws[lcb + 3][lr] = wv.w;
        __syncthreads();

#pragma unroll
        for (int kk = 0; kk < BK; kk++) {
            float4 af = *(const float4*)&As[kk][ty * 4];
            float4 bf = *(const float4*)&Ws[kk][tx * 4];
            float a_[4] = {af.x, af.y, af.z, af.w};
            float b_[4] = {bf.x, bf.y, bf.z, bf.w};
#pragma unroll
            for (int i = 0; i < 4; i++)
#pragma unroll
                for (int j = 0; j < 4; j++)
                    acc[i][j] = fmaf(a_[i], b_[j], acc[i][j]);
        }
        __syncthreads();
    }

    float4 bv = *(const float4*)&bias[bn + tx * 4];
#pragma unroll
    for (int i = 0; i < 4; i++) {
        float4 o = make_float4(acc[i][0] + bv.x, acc[i][1] + bv.y,
                               acc[i][2] + bv.z, acc[i][3] + bv.w);
        *(float4*)&C[(size_t)(bm + ty * 4 + i) * N + bn + tx * 4] = o;
    }
}

// ---------------------------------------------------------------------------
// Flash attention, fp32. One block = one (b,h) x 64-query tile.
// smem: qs[d][i], ks[d][j] (transposed), ps[i][j], vs[j][dd] (natural).
// 256 threads, 4x4 micro-tiles for both QK^T and PV GEMMs.
// ---------------------------------------------------------------------------
__global__ __launch_bounds__(256) void flash_attn_kernel(
    const float* __restrict__ Q,
    const float* __restrict__ K,
    const float* __restrict__ V,
    float* __restrict__ O)
{
    extern __shared__ float sm[];
    float* qs = sm;              // 64*64
    float* ks = sm + 4096;       // 64*64
    float* ps = sm + 8192;       // 64*64
    float* vs = sm + 12288;      // 64*64

    const int bh = blockIdx.y;
    const int b = bh / HH;
    const int h = bh % HH;
    const int q0 = blockIdx.x * 64;

    const float* Qb = Q + (size_t)b * SS * DM + h * DK;
    const float* Kb = K + (size_t)b * SS * DM + h * DK;
    const float* Vb = V + (size_t)b * SS * DM + h * DK;
    float*       Ob = O + (size_t)b * SS * DM + h * DK;

    const int tid = threadIdx.x;
    const int tx = tid & 15;
    const int ty = tid >> 4;
    const int lr  = tid >> 2;        // 0..63
    const int lcb = (tid & 3) * 4;   // 0,4,8,12

    // load Q tile transposed, pre-scaled by 1/sqrt(Dk)
#pragma unroll
    for (int p = 0; p < 4; p++) {
        const int c = lcb + p * 16;
        float4 v4 = *(const float4*)&Qb[(size_t)(q0 + lr) * DM + c];
        qs[(c + 0) * 64 + lr] = v4.x * 0.125f;
        qs[(c + 1) * 64 + lr] = v4.y * 0.125f;
        qs[(c + 2) * 64 + lr] = v4.z * 0.125f;
        qs[(c + 3) * 64 + lr] = v4.w * 0.125f;
    }

    float m_[4], l_[4], acc[4][4];
#pragma unroll
    for (int i = 0; i < 4; i++) {
        m_[i] = -1e30f;
        l_[i] = 0.0f;
#pragma unroll
        for (int j = 0; j < 4; j++) acc[i][j] = 0.0f;
    }

    for (int t = 0; t < SS; t += 64) {
        __syncthreads();   // previous ps/ks/vs reads complete
#pragma unroll
        for (int p = 0; p < 4; p++) {
            const int c = lcb + p * 16;
            float4 k4 = *(const float4*)&Kb[(size_t)(t + lr) * DM + c];
            ks[(c + 0) * 64 + lr] = k4.x;
            ks[(c + 1) * 64 + lr] = k4.y;
            ks[(c + 2) * 64 + lr] = k4.z;
            ks[(c + 3) * 64 + lr] = k4.w;
            float4 v4 = *(const float4*)&Vb[(size_t)(t + lr) * DM + c];
            *(float4*)&vs[lr * 64 + c] = v4;
        }
        __syncthreads();

        // s = q @ k^T  (contraction over d)
        float s[4][4];
#pragma unroll
        for (int i = 0; i < 4; i++)
#pragma unroll
            for (int j = 0; j < 4; j++) s[i][j] = 0.0f;

#pragma unroll
        for (int d = 0; d < 64; d++) {
            float4 af = *(const float4*)&qs[d * 64 + ty * 4];
            float4 bf = *(const float4*)&ks[d * 64 + tx * 4];
            float a_[4] = {af.x, af.y, af.z, af.w};
            float b_[4] = {bf.x, bf.y, bf.z, bf.w};
#pragma unroll
            for (int i = 0; i < 4; i++)
#pragma unroll
                for (int j = 0; j < 4; j++)
                    s[i][j] = fmaf(a_[i], b_[j], s[i][j]);
        }

        // online softmax (row reductions across the 16 tx lanes)
#pragma unroll
        for (int i = 0; i < 4; i++) {
            float rm = fmaxf(fmaxf(s[i][0], s[i][1]), fmaxf(s[i][2], s[i][3]));
            rm = fmaxf(rm, __shfl_xor_sync(0xffffffffu, rm, 1));
            rm = fmaxf(rm, __shfl_xor_sync(0xffffffffu, rm, 2));
            rm = fmaxf(rm, __shfl_xor_sync(0xffffffffu, rm, 4));
            rm = fmaxf(rm, __shfl_xor_sync(0xffffffffu, rm, 8));
            float mn = fmaxf(m_[i], rm);
            float p0 = __expf(s[i][0] - mn);
            float p1 = __expf(s[i][1] - mn);
            float p2 = __expf(s[i][2] - mn);
            float p3 = __expf(s[i][3] - mn);
            float rs = p0 + p1 + p2 + p3;
            rs += __shfl_xor_sync(0xffffffffu, rs, 1);
            rs += __shfl_xor_sync(0xffffffffu, rs, 2);
            rs += __shfl_xor_sync(0xffffffffu, rs, 4);
            rs += __shfl_xor_sync(0xffffffffu, rs, 8);
            float f = __expf(m_[i] - mn);
            m_[i] = mn;
            l_[i] = l_[i] * f + rs;
            acc[i][0] *= f; acc[i][1] *= f; acc[i][2] *= f; acc[i][3] *= f;
            s[i][0] = p0; s[i][1] = p1; s[i][2] = p2; s[i][3] = p3;
        }

        // write p tile (natural layout), vectorized
#pragma unroll
        for (int i = 0; i < 4; i++)
            *(float4*)&ps[(ty * 4 + i) * 64 + tx * 4] =
                make_float4(s[i][0], s[i][1], s[i][2], s[i][3]);
        __syncthreads();

        // acc += p @ v  (contraction over j, unrolled by 4 for LDS.128)
#pragma unroll
        for (int j = 0; j < 64; j += 4) {
            float a_[4][4];
#pragma unroll
            for (int i = 0; i < 4; i++) {
                float4 a4 = *(const float4*)&ps[(ty * 4 + i) * 64 + j];
                a_[i][0] = a4.x; a_[i][1] = a4.y; a_[i][2] = a4.z; a_[i][3] = a4.w;
            }
#pragma unroll
            for (int jj = 0; jj < 4; jj++) {
                float4 b4 = *(const float4*)&vs[(j + jj) * 64 + tx * 4];
#pragma unroll
                for (int i = 0; i < 4; i++) {
                    acc[i][0] = fmaf(a_[i][jj], b4.x, acc[i][0]);
                    acc[i][1] = fmaf(a_[i][jj], b4.y, acc[i][1]);
                    acc[i][2] = fmaf(a_[i][jj], b4.z, acc[i][2]);
                    acc[i][3] = fmaf(a_[i][jj], b4.w, acc[i][3]);
                }
            }
        }
    }

    // normalize and write context in merged-head layout [b, s, h*64+dd]
#pragma unroll
    for (int i = 0; i < 4; i++) {
        float inv = 1.0f / l_[i];
        float4 o = make_float4(acc[i][0] * inv, acc[i][1] * inv,
                               acc[i][2] * inv, acc[i][3] * inv);
        *(float4*)&Ob[(size_t)(q0 + ty * 4 + i) * DM + tx * 4] = o;
    }
}

// ---------------------------------------------------------------------------
extern "C" void kernel_launch(void* const* d_in, const int* in_sizes, int n_in,
                              void* d_out, int out_size)
{
    const float* query = (const float*)d_in[0];
    const float* key   = (const float*)d_in[1];
    const float* value = (const float*)d_in[2];
    const float* Wq    = (const float*)d_in[3];   // [H,Dk,D] == [768,768]
    const float* bq    = (const float*)d_in[4];   // [H,Dk]  == [768]
    const float* Wk    = (const float*)d_in[5];
    const float* bk    = (const float*)d_in[6];
    const float* Wv    = (const float*)d_in[7];
    const float* bv    = (const float*)d_in[8];
    const float* Wo    = (const float*)d_in[9];   // [768,768]
    const float* bo    = (const float*)d_in[10];  // [768]
    float* out = (float*)d_out;

    static float *qp = nullptr, *kp = nullptr, *vp = nullptr, *cp = nullptr;
    static bool init_done = false;
    if (!init_done) {
        cudaGetSymbolAddress((void**)&qp, g_q);
        cudaGetSymbolAddress((void**)&kp, g_k);
        cudaGetSymbolAddress((void**)&vp, g_v);
        cudaGetSymbolAddress((void**)&cp, g_ctx);
        cudaFuncSetAttribute(flash_attn_kernel,
                             cudaFuncAttributeMaxDynamicSharedMemorySize,
                             4 * 64 * 64 * (int)sizeof(float));
        init_done = true;
    }

    dim3 tpb(256);
    dim3 gproj(DM / TILE, MROWS / TILE);   // (12, 64)

    sgemm_bias_kernel<<<gproj, tpb>>>(query, Wq, bq, qp, MROWS, DM, DM);
    sgemm_bias_kernel<<<gproj, tpb>>>(key,   Wk, bk, kp, MROWS, DM, DM);
    sgemm_bias_kernel<<<gproj, tpb>>>(value, Wv, bv, vp, MROWS, DM, DM);

    size_t smem = 4 * 64 * 64 * sizeof(float);  // 64 KB
    dim3 gattn(SS / 64, BB * HH);               // (32, 24)
    flash_attn_kernel<<<gattn, tpb, smem>>>(qp, kp, vp, cp);

    sgemm_bias_kernel<<<gproj, tpb>>>(cp, Wo, bo, out, MROWS, DM, DM);
}

// round 14
// speedup vs baseline: 1.3412x; 1.3412x over previous
#include <cuda_runtime.h>
#include <cuda_bf16.h>
#include <cstdint>

// Problem constants
#define BB 2
#define SS 2048
#define HH 12
#define DK 64
#define DM 768
#define MROWS (BB * SS)        // 4096
#define ELEMS (MROWS * DM)     // 3,145,728

// Scratch (no allocation allowed -> __device__ globals)
__device__ float g_q[ELEMS];
__device__ float g_k[ELEMS];
__device__ float g_v[ELEMS];
__device__ float g_ctx[ELEMS];

// ===========================================================================
// Warp-level bf16 tensor-core GEMM (mma.sync, baseline PTX feature set):
//   C[M,N] = A[M,K] @ W[N,K]^T + bias[N],  fp32-accurate via bf16 hi/lo split
// CTA 128x128, 8 warps (2M x 4N), warp tile 64x32 (4x4 of m16n8k16).
// K staged in 32-wide chunks = 2 slabs of k16; smem rows 48B (conflict-free).
// ===========================================================================

__device__ __forceinline__ uint32_t smem_u32(const void* p) {
    uint32_t a;
    asm("{ .reg .u64 t; cvta.to.shared.u64 t, %1; cvt.u32.u64 %0, t; }"
        : "=r"(a) : "l"(p));
    return a;
}

#define LDSM4(d0, d1, d2, d3, a)                                         \
    asm volatile("ldmatrix.sync.aligned.m8n8.x4.shared.b16 "             \
                 "{%0,%1,%2,%3}, [%4];"                                  \
                 : "=r"(d0), "=r"(d1), "=r"(d2), "=r"(d3) : "r"(a))

#define MMA16816(c, a, b0, b1)                                           \
    asm volatile("mma.sync.aligned.m16n8k16.row.col.f32.bf16.bf16.f32 "  \
                 "{%0,%1,%2,%3}, {%4,%5,%6,%7}, {%8,%9}, {%0,%1,%2,%3};" \
                 : "+f"((c)[0]), "+f"((c)[1]), "+f"((c)[2]), "+f"((c)[3])\
                 : "r"((a)[0]), "r"((a)[1]), "r"((a)[2]), "r"((a)[3]),   \
                   "r"(b0), "r"(b1))

// smem layout: 4 matrices (A_hi, A_lo, W_hi, W_lo) x 2 k16-slabs
#define RB   48                         // bytes per 16-k row (24 bf16, padded)
#define SLAB (128 * RB)                 // 6144 bytes
#define AHI  0
#define ALO  (2 * SLAB)
#define WHI  (4 * SLAB)
#define WLO  (6 * SLAB)
#define GSMEM (8 * SLAB)                // 49152 bytes

struct GemmArgs { const float* A; const float* W; const float* b; float* C; };

// 8 consecutive fp32 -> 8 bf16 hi (16B) + 8 bf16 lo (16B)
__device__ __forceinline__ void cvt8(const float* s, uint4& hi, uint4& lo) {
    float4 x0 = *(const float4*)(s);
    float4 x1 = *(const float4*)(s + 4);
    float f[8] = {x0.x, x0.y, x0.z, x0.w, x1.x, x1.y, x1.z, x1.w};
    uint32_t hp[4], lp[4];
#pragma unroll
    for (int i = 0; i < 4; i++) {
        __nv_bfloat16 h0 = __float2bfloat16(f[2 * i]);
        __nv_bfloat16 h1 = __float2bfloat16(f[2 * i + 1]);
        float l0 = f[2 * i]     - __bfloat162float(h0);
        float l1 = f[2 * i + 1] - __bfloat162float(h1);
        __nv_bfloat162 hh = __halves2bfloat162(h0, h1);
        __nv_bfloat162 ll = __halves2bfloat162(__float2bfloat16(l0),
                                               __float2bfloat16(l1));
        hp[i] = *(uint32_t*)&hh;
        lp[i] = *(uint32_t*)&ll;
    }
    hi = make_uint4(hp[0], hp[1], hp[2], hp[3]);
    lo = make_uint4(lp[0], lp[1], lp[2], lp[3]);
}

__global__ __launch_bounds__(256, 1) void gemm_hmma(
    GemmArgs ga0, GemmArgs ga1, GemmArgs ga2)
{
    extern __shared__ char sm[];
    const GemmArgs g = (blockIdx.z == 0) ? ga0 : (blockIdx.z == 1) ? ga1 : ga2;
    const int tid  = threadIdx.x;
    const int lane = tid & 31;
    const int wid  = tid >> 5;
    const int wm   = wid >> 2;          // 0..1  (M warp)
    const int wn   = wid & 3;           // 0..3  (N warp)
    const int grp  = lane >> 2;         // 0..7
    const int tig  = lane & 3;          // 0..3
    const int sub  = lane >> 3;         // 0..3  (ldmatrix octet)
    const int r8   = lane & 7;
    const int bm = blockIdx.y * 128;
    const int bn = blockIdx.x * 128;
    const uint32_t sb = smem_u32(sm);

    // gmem load/convert mapping: 2 threads per row, 16 k each
    const int row = tid >> 1;           // 0..127
    const int kh  = tid & 1;            // slab select
    const float* arow = g.A + (size_t)(bm + row) * DM + kh * 16;
    const float* wrow = g.W + (size_t)(bn + row) * DM + kh * 16;
    char* a_hi = sm + AHI + kh * SLAB + row * RB;
    char* a_lo = sm + ALO + kh * SLAB + row * RB;
    char* w_hi = sm + WHI + kh * SLAB + row * RB;
    char* w_lo = sm + WLO + kh * SLAB + row * RB;

    // ldmatrix per-lane addresses (per m-tile / n-pair), relative to slab base
    uint32_t aoff[4], woff[2];
#pragma unroll
    for (int mt = 0; mt < 4; mt++) {
        int rr = wm * 64 + mt * 16 + (sub & 1) * 8 + r8;
        aoff[mt] = (uint32_t)(rr * RB + (sub >> 1) * 16);
    }
#pragma unroll
    for (int np = 0; np < 2; np++) {
        int nr = wn * 32 + np * 16 + (sub >> 1) * 8 + r8;
        woff[np] = (uint32_t)(nr * RB + (sub & 1) * 16);
    }

    float acc[4][4][4];
#pragma unroll
    for (int i = 0; i < 4; i++)
#pragma unroll
        for (int j = 0; j < 4; j++)
#pragma unroll
            for (int q = 0; q < 4; q++) acc[i][j][q] = 0.0f;

    const int NCH = DM / 32;            // 24
    for (int c = 0; c < NCH; c++) {
        if (c) __syncthreads();         // previous slab reads complete
        const int k0 = c * 32;
        uint4 hi, lo;
#pragma unroll
        for (int u = 0; u < 2; u++) {
            cvt8(arow + k0 + u * 8, hi, lo);
            *(uint4*)(a_hi + u * 16) = hi;
            *(uint4*)(a_lo + u * 16) = lo;
            cvt8(wrow + k0 + u * 8, hi, lo);
            *(uint4*)(w_hi + u * 16) = hi;
            *(uint4*)(w_lo + u * 16) = lo;
        }
        __syncthreads();

#pragma unroll
        for (int sl = 0; sl < 2; sl++) {
            const uint32_t ab = sb + sl * SLAB;
            uint32_t ahi[4][4], alo[4][4], whi[2][4], wlo[2][4];
#pragma unroll
            for (int mt = 0; mt < 4; mt++) {
                LDSM4(ahi[mt][0], ahi[mt][1], ahi[mt][2], ahi[mt][3],
                      ab + AHI + aoff[mt]);
                LDSM4(alo[mt][0], alo[mt][1], alo[mt][2], alo[mt][3],
                      ab + ALO + aoff[mt]);
            }
#pragma unroll
            for (int np = 0; np < 2; np++) {
                LDSM4(whi[np][0], whi[np][1], whi[np][2], whi[np][3],
                      ab + WHI + woff[np]);
                LDSM4(wlo[np][0], wlo[np][1], wlo[np][2], wlo[np][3],
                      ab + WLO + woff[np]);
            }
#pragma unroll
            for (int mt = 0; mt < 4; mt++)
#pragma unroll
                for (int nt = 0; nt < 4; nt++) {
                    const int np = nt >> 1, h = (nt & 1) * 2;
                    MMA16816(acc[mt][nt], ahi[mt], whi[np][h], whi[np][h + 1]);
                    MMA16816(acc[mt][nt], alo[mt], whi[np][h], whi[np][h + 1]);
                    MMA16816(acc[mt][nt], ahi[mt], wlo[np][h], wlo[np][h + 1]);
                }
        }
    }

    // Epilogue: c0,c1 = (row grp, col 2tig,+1); c2,c3 = (row grp+8, same cols)
#pragma unroll
    for (int mt = 0; mt < 4; mt++) {
        const int row0 = bm + wm * 64 + mt * 16 + grp;
#pragma unroll
        for (int nt = 0; nt < 4; nt++) {
            const int col = bn + wn * 32 + nt * 8 + 2 * tig;
            float2 bv = *(const float2*)&g.b[col];
            float2 o0, o1;
            o0.x = acc[mt][nt][0] + bv.x;
            o0.y = acc[mt][nt][1] + bv.y;
            o1.x = acc[mt][nt][2] + bv.x;
            o1.y = acc[mt][nt][3] + bv.y;
            *(float2*)&g.C[(size_t)row0 * DM + col]       = o0;
            *(float2*)&g.C[(size_t)(row0 + 8) * DM + col] = o1;
        }
    }
}

// ===========================================================================
// Flash attention, fp32 (unchanged from passing R3 kernel; ~790us,
// measured AT its FFMA floor ~65 TF/s. Conversion to mma.sync is gated on
// the HMMA rate this round's gemm profile will measure: EV(flash-HMMA) is
// ~neutral (850us) under the current rate prior, so fp32 stays for now.)
// ===========================================================================
__global__ __launch_bounds__(256) void flash_attn_kernel(
    const float* __restrict__ Q,
    const float* __restrict__ K,
    const float* __restrict__ V,
    float* __restrict__ O)
{
    extern __shared__ float smf[];
    float* qs = smf;              // 64*64
    float* ks = smf + 4096;       // 64*64
    float* ps = smf + 8192;       // 64*64
    float* vs = smf + 12288;      // 64*64

    const int bh = blockIdx.y;
    const int b = bh / HH;
    const int h = bh % HH;
    const int q0 = blockIdx.x * 64;

    const float* Qb = Q + (size_t)b * SS * DM + h * DK;
    const float* Kb = K + (size_t)b * SS * DM + h * DK;
    const float* Vb = V + (size_t)b * SS * DM + h * DK;
    float*       Ob = O + (size_t)b * SS * DM + h * DK;

    const int tid = threadIdx.x;
    const int tx = tid & 15;
    const int ty = tid >> 4;
    const int lr  = tid >> 2;
    const int lcb = (tid & 3) * 4;

#pragma unroll
    for (int p = 0; p < 4; p++) {
        const int c = lcb + p * 16;
        float4 v4 = *(const float4*)&Qb[(size_t)(q0 + lr) * DM + c];
        qs[(c + 0) * 64 + lr] = v4.x * 0.125f;
        qs[(c + 1) * 64 + lr] = v4.y * 0.125f;
        qs[(c + 2) * 64 + lr] = v4.z * 0.125f;
        qs[(c + 3) * 64 + lr] = v4.w * 0.125f;
    }

    float m_[4], l_[4], acc[4][4];
#pragma unroll
    for (int i = 0; i < 4; i++) {
        m_[i] = -1e30f;
        l_[i] = 0.0f;
#pragma unroll
        for (int j = 0; j < 4; j++) acc[i][j] = 0.0f;
    }

    for (int t = 0; t < SS; t += 64) {
        __syncthreads();
#pragma unroll
        for (int p = 0; p < 4; p++) {
            const int c = lcb + p * 16;
            float4 k4 = *(const float4*)&Kb[(size_t)(t + lr) * DM + c];
            ks[(c + 0) * 64 + lr] = k4.x;
            ks[(c + 1) * 64 + lr] = k4.y;
            ks[(c + 2) * 64 + lr] = k4.z;
            ks[(c + 3) * 64 + lr] = k4.w;
            float4 v4 = *(const float4*)&Vb[(size_t)(t + lr) * DM + c];
            *(float4*)&vs[lr * 64 + c] = v4;
        }
        __syncthreads();

        float s[4][4];
#pragma unroll
        for (int i = 0; i < 4; i++)
#pragma unroll
            for (int j = 0; j < 4; j++) s[i][j] = 0.0f;

#pragma unroll
        for (int d = 0; d < 64; d++) {
            float4 af = *(const float4*)&qs[d * 64 + ty * 4];
            float4 bf = *(const float4*)&ks[d * 64 + tx * 4];
            float a_[4] = {af.x, af.y, af.z, af.w};
            float b_[4] = {bf.x, bf.y, bf.z, bf.w};
#pragma unroll
            for (int i = 0; i < 4; i++)
#pragma unroll
                for (int j = 0; j < 4; j++)
                    s[i][j] = fmaf(a_[i], b_[j], s[i][j]);
        }

#pragma unroll
        for (int i = 0; i < 4; i++) {
            float rm = fmaxf(fmaxf(s[i][0], s[i][1]), fmaxf(s[i][2], s[i][3]));
            rm = fmaxf(rm, __shfl_xor_sync(0xffffffffu, rm, 1));
            rm = fmaxf(rm, __shfl_xor_sync(0xffffffffu, rm, 2));
            rm = fmaxf(rm, __shfl_xor_sync(0xffffffffu, rm, 4));
            rm = fmaxf(rm, __shfl_xor_sync(0xffffffffu, rm, 8));
            float mn = fmaxf(m_[i], rm);
            float p0 = __expf(s[i][0] - mn);
            float p1 = __expf(s[i][1] - mn);
            float p2 = __expf(s[i][2] - mn);
            float p3 = __expf(s[i][3] - mn);
            float rs = p0 + p1 + p2 + p3;
            rs += __shfl_xor_sync(0xffffffffu, rs, 1);
            rs += __shfl_xor_sync(0xffffffffu, rs, 2);
            rs += __shfl_xor_sync(0xffffffffu, rs, 4);
            rs += __shfl_xor_sync(0xffffffffu, rs, 8);
            float f = __expf(m_[i] - mn);
            m_[i] = mn;
            l_[i] = l_[i] * f + rs;
            acc[i][0] *= f; acc[i][1] *= f; acc[i][2] *= f; acc[i][3] *= f;
            s[i][0] = p0; s[i][1] = p1; s[i][2] = p2; s[i][3] = p3;
        }

#pragma unroll
        for (int i = 0; i < 4; i++)
            *(float4*)&ps[(ty * 4 + i) * 64 + tx * 4] =
                make_float4(s[i][0], s[i][1], s[i][2], s[i][3]);
        __syncthreads();

#pragma unroll
        for (int j = 0; j < 64; j += 4) {
            float a_[4][4];
#pragma unroll
            for (int i = 0; i < 4; i++) {
                float4 a4 = *(const float4*)&ps[(ty * 4 + i) * 64 + j];
                a_[i][0] = a4.x; a_[i][1] = a4.y; a_[i][2] = a4.z; a_[i][3] = a4.w;
            }
#pragma unroll
            for (int jj = 0; jj < 4; jj++) {
                float4 b4 = *(const float4*)&vs[(j + jj) * 64 + tx * 4];
#pragma unroll
                for (int i = 0; i < 4; i++) {
                    acc[i][0] = fmaf(a_[i][jj], b4.x, acc[i][0]);
                    acc[i][1] = fmaf(a_[i][jj], b4.y, acc[i][1]);
                    acc[i][2] = fmaf(a_[i][jj], b4.z, acc[i][2]);
                    acc[i][3] = fmaf(a_[i][jj], b4.w, acc[i][3]);
                }
            }
        }
    }

#pragma unroll
    for (int i = 0; i < 4; i++) {
        float inv = 1.0f / l_[i];
        float4 o = make_float4(acc[i][0] * inv, acc[i][1] * inv,
                               acc[i][2] * inv, acc[i][3] * inv);
        *(float4*)&Ob[(size_t)(q0 + ty * 4 + i) * DM + tx * 4] = o;
    }
}

// ===========================================================================
extern "C" void kernel_launch(void* const* d_in, const int* in_sizes, int n_in,
                              void* d_out, int out_size)
{
    const float* query = (const float*)d_in[0];
    const float* key   = (const float*)d_in[1];
    const float* value = (const float*)d_in[2];
    const float* Wq    = (const float*)d_in[3];
    const float* bq    = (const float*)d_in[4];
    const float* Wk    = (const float*)d_in[5];
    const float* bk    = (const float*)d_in[6];
    const float* Wv    = (const float*)d_in[7];
    const float* bv    = (const float*)d_in[8];
    const float* Wo    = (const float*)d_in[9];
    const float* bo    = (const float*)d_in[10];
    float* out = (float*)d_out;

    static float *qp = nullptr, *kp = nullptr, *vp = nullptr, *cp = nullptr;
    static bool init_done = false;
    if (!init_done) {
        cudaGetSymbolAddress((void**)&qp, g_q);
        cudaGetSymbolAddress((void**)&kp, g_k);
        cudaGetSymbolAddress((void**)&vp, g_v);
        cudaGetSymbolAddress((void**)&cp, g_ctx);
        cudaFuncSetAttribute(flash_attn_kernel,
                             cudaFuncAttributeMaxDynamicSharedMemorySize,
                             4 * 64 * 64 * (int)sizeof(float));
        cudaFuncSetAttribute(gemm_hmma,
                             cudaFuncAttributeMaxDynamicSharedMemorySize, GSMEM);
        init_done = true;
    }

    GemmArgs aq{query, Wq, bq, qp};
    GemmArgs ak{key,   Wk, bk, kp};
    GemmArgs av{value, Wv, bv, vp};
    GemmArgs ao{cp,    Wo, bo, out};

    // QKV projections: one batched tensor-core GEMM launch (z selects input)
    dim3 gqkv(DM / 128, MROWS / 128, 3);     // (6, 32, 3)
    gemm_hmma<<<gqkv, 256, GSMEM>>>(aq, ak, av);

    // Flash attention (fp32)
    size_t smem = 4 * 64 * 64 * sizeof(float);
    dim3 gattn(SS / 64, BB * HH);            // (32, 24)
    flash_attn_kernel<<<gattn, 256, smem>>>(qp, kp, vp, cp);

    // Output projection
    dim3 gout(DM / 128, MROWS / 128, 1);     // (6, 32)
    gemm_hmma<<<gout, 256, GSMEM>>>(ao, ao, ao);
}

// round 15
// speedup vs baseline: 2.4384x; 1.8180x over previous
#include <cuda_runtime.h>
#include <cuda_bf16.h>
#include <cstdint>

// Problem constants
#define BB 2
#define SS 2048
#define HH 12
#define DK 64
#define DM 768
#define MROWS (BB * SS)        // 4096
#define ELEMS (MROWS * DM)     // 3,145,728

// Scratch (no allocation allowed -> __device__ globals)
__device__ float g_q[ELEMS];
__device__ float g_k[ELEMS];
__device__ float g_v[ELEMS];
__device__ float g_ctx[ELEMS];

__device__ __forceinline__ uint32_t smem_u32(const void* p) {
    uint32_t a;
    asm("{ .reg .u64 t; cvta.to.shared.u64 t, %1; cvt.u32.u64 %0, t; }"
        : "=r"(a) : "l"(p));
    return a;
}

#define LDSM4(d0, d1, d2, d3, a)                                         \
    asm volatile("ldmatrix.sync.aligned.m8n8.x4.shared.b16 "             \
                 "{%0,%1,%2,%3}, [%4];"                                  \
                 : "=r"(d0), "=r"(d1), "=r"(d2), "=r"(d3) : "r"(a))

#define LDSM4T(d0, d1, d2, d3, a)                                        \
    asm volatile("ldmatrix.sync.aligned.m8n8.x4.trans.shared.b16 "       \
                 "{%0,%1,%2,%3}, [%4];"                                  \
                 : "=r"(d0), "=r"(d1), "=r"(d2), "=r"(d3) : "r"(a))

#define MMA16816(c, a, b0, b1)                                           \
    asm volatile("mma.sync.aligned.m16n8k16.row.col.f32.bf16.bf16.f32 "  \
                 "{%0,%1,%2,%3}, {%4,%5,%6,%7}, {%8,%9}, {%0,%1,%2,%3};" \
                 : "+f"((c)[0]), "+f"((c)[1]), "+f"((c)[2]), "+f"((c)[3])\
                 : "r"((a)[0]), "r"((a)[1]), "r"((a)[2]), "r"((a)[3]),   \
                   "r"(b0), "r"(b1))

// ===========================================================================
// GEMM (validated R14: 196 TF/s eff., rel_err 3.5e-6) — UNCHANGED
// ===========================================================================
#define RB   48
#define SLAB (128 * RB)
#define AHI  0
#define ALO  (2 * SLAB)
#define WHI  (4 * SLAB)
#define WLO  (6 * SLAB)
#define GSMEM (8 * SLAB)

struct GemmArgs { const float* A; const float* W; const float* b; float* C; };

__device__ __forceinline__ void cvt8(const float* s, uint4& hi, uint4& lo) {
    float4 x0 = *(const float4*)(s);
    float4 x1 = *(const float4*)(s + 4);
    float f[8] = {x0.x, x0.y, x0.z, x0.w, x1.x, x1.y, x1.z, x1.w};
    uint32_t hp[4], lp[4];
#pragma unroll
    for (int i = 0; i < 4; i++) {
        __nv_bfloat16 h0 = __float2bfloat16(f[2 * i]);
        __nv_bfloat16 h1 = __float2bfloat16(f[2 * i + 1]);
        float l0 = f[2 * i]     - __bfloat162float(h0);
        float l1 = f[2 * i + 1] - __bfloat162float(h1);
        __nv_bfloat162 hh = __halves2bfloat162(h0, h1);
        __nv_bfloat162 ll = __halves2bfloat162(__float2bfloat16(l0),
                                               __float2bfloat16(l1));
        hp[i] = *(uint32_t*)&hh;
        lp[i] = *(uint32_t*)&ll;
    }
    hi = make_uint4(hp[0], hp[1], hp[2], hp[3]);
    lo = make_uint4(lp[0], lp[1], lp[2], lp[3]);
}

__global__ __launch_bounds__(256, 1) void gemm_hmma(
    GemmArgs ga0, GemmArgs ga1, GemmArgs ga2)
{
    extern __shared__ char sm[];
    const GemmArgs g = (blockIdx.z == 0) ? ga0 : (blockIdx.z == 1) ? ga1 : ga2;
    const int tid  = threadIdx.x;
    const int lane = tid & 31;
    const int wid  = tid >> 5;
    const int wm   = wid >> 2;
    const int wn   = wid & 3;
    const int grp  = lane >> 2;
    const int tig  = lane & 3;
    const int sub  = lane >> 3;
    const int r8   = lane & 7;
    const int bm = blockIdx.y * 128;
    const int bn = blockIdx.x * 128;
    const uint32_t sb = smem_u32(sm);

    const int row = tid >> 1;
    const int kh  = tid & 1;
    const float* arow = g.A + (size_t)(bm + row) * DM + kh * 16;
    const float* wrow = g.W + (size_t)(bn + row) * DM + kh * 16;
    char* a_hi = sm + AHI + kh * SLAB + row * RB;
    char* a_lo = sm + ALO + kh * SLAB + row * RB;
    char* w_hi = sm + WHI + kh * SLAB + row * RB;
    char* w_lo = sm + WLO + kh * SLAB + row * RB;

    uint32_t aoff[4], woff[2];
#pragma unroll
    for (int mt = 0; mt < 4; mt++) {
        int rr = wm * 64 + mt * 16 + (sub & 1) * 8 + r8;
        aoff[mt] = (uint32_t)(rr * RB + (sub >> 1) * 16);
    }
#pragma unroll
    for (int np = 0; np < 2; np++) {
        int nr = wn * 32 + np * 16 + (sub >> 1) * 8 + r8;
        woff[np] = (uint32_t)(nr * RB + (sub & 1) * 16);
    }

    float acc[4][4][4];
#pragma unroll
    for (int i = 0; i < 4; i++)
#pragma unroll
        for (int j = 0; j < 4; j++)
#pragma unroll
            for (int q = 0; q < 4; q++) acc[i][j][q] = 0.0f;

    const int NCH = DM / 32;
    for (int c = 0; c < NCH; c++) {
        if (c) __syncthreads();
        const int k0 = c * 32;
        uint4 hi, lo;
#pragma unroll
        for (int u = 0; u < 2; u++) {
            cvt8(arow + k0 + u * 8, hi, lo);
            *(uint4*)(a_hi + u * 16) = hi;
            *(uint4*)(a_lo + u * 16) = lo;
            cvt8(wrow + k0 + u * 8, hi, lo);
            *(uint4*)(w_hi + u * 16) = hi;
            *(uint4*)(w_lo + u * 16) = lo;
        }
        __syncthreads();

#pragma unroll
        for (int sl = 0; sl < 2; sl++) {
            const uint32_t ab = sb + sl * SLAB;
            uint32_t ahi[4][4], alo[4][4], whi[2][4], wlo[2][4];
#pragma unroll
            for (int mt = 0; mt < 4; mt++) {
                LDSM4(ahi[mt][0], ahi[mt][1], ahi[mt][2], ahi[mt][3],
                      ab + AHI + aoff[mt]);
                LDSM4(alo[mt][0], alo[mt][1], alo[mt][2], alo[mt][3],
                      ab + ALO + aoff[mt]);
            }
#pragma unroll
            for (int np = 0; np < 2; np++) {
                LDSM4(whi[np][0], whi[np][1], whi[np][2], whi[np][3],
                      ab + WHI + woff[np]);
                LDSM4(wlo[np][0], wlo[np][1], wlo[np][2], wlo[np][3],
                      ab + WLO + woff[np]);
            }
#pragma unroll
            for (int mt = 0; mt < 4; mt++)
#pragma unroll
                for (int nt = 0; nt < 4; nt++) {
                    const int np = nt >> 1, h = (nt & 1) * 2;
                    MMA16816(acc[mt][nt], ahi[mt], whi[np][h], whi[np][h + 1]);
                    MMA16816(acc[mt][nt], alo[mt], whi[np][h], whi[np][h + 1]);
                    MMA16816(acc[mt][nt], ahi[mt], wlo[np][h], wlo[np][h + 1]);
                }
        }
    }

#pragma unroll
    for (int mt = 0; mt < 4; mt++) {
        const int row0 = bm + wm * 64 + mt * 16 + grp;
#pragma unroll
        for (int nt = 0; nt < 4; nt++) {
            const int col = bn + wn * 32 + nt * 8 + 2 * tig;
            float2 bv = *(const float2*)&g.b[col];
            float2 o0, o1;
            o0.x = acc[mt][nt][0] + bv.x;
            o0.y = acc[mt][nt][1] + bv.y;
            o1.x = acc[mt][nt][2] + bv.x;
            o1.y = acc[mt][nt][3] + bv.y;
            *(float2*)&g.C[(size_t)row0 * DM + col]       = o0;
            *(float2*)&g.C[(size_t)(row0 + 8) * DM + col] = o1;
        }
    }
}

// ===========================================================================
// Flash attention on mma.sync (bf16 hi/lo splits everywhere; fp32 softmax).
// CTA = 128 queries, 8 warps, each warp: m16 x full 64-key tile.
// smem rows padded to 144B (36r mod 32 distinct -> conflict-free ldmatrix).
// P stays in registers: S C-frags repack directly into PV A-frags.
// V consumed via ldmatrix.trans (row-major [key][dk] -> B-frag n=dk,k=key).
// ===========================================================================
#define RB2 144
#define FQ_HI 0
#define FQ_LO (FQ_HI + 128 * RB2)      // 18432
#define FK_HI (FQ_LO + 128 * RB2)      // 36864
#define FK_LO (FK_HI + 64 * RB2)       // 46080
#define FV_HI (FK_LO + 64 * RB2)       // 55296
#define FV_LO (FV_HI + 64 * RB2)       // 64512
#define FSMEM (FV_LO + 64 * RB2)       // 73728

// 8 fp32 -> scaled bf16 hi/lo, stored at plain (non-swizzled) 16B offsets
__device__ __forceinline__ void cvt8p(const float* s, char* dhi, char* dlo,
                                      float scale) {
    float4 x0 = *(const float4*)(s);
    float4 x1 = *(const float4*)(s + 4);
    float f[8] = {x0.x * scale, x0.y * scale, x0.z * scale, x0.w * scale,
                  x1.x * scale, x1.y * scale, x1.z * scale, x1.w * scale};
    uint32_t hp[4], lp[4];
#pragma unroll
    for (int i = 0; i < 4; i++) {
        __nv_bfloat16 h0 = __float2bfloat16(f[2 * i]);
        __nv_bfloat16 h1 = __float2bfloat16(f[2 * i + 1]);
        float l0 = f[2 * i]     - __bfloat162float(h0);
        float l1 = f[2 * i + 1] - __bfloat162float(h1);
        __nv_bfloat162 hh = __halves2bfloat162(h0, h1);
        __nv_bfloat162 ll = __halves2bfloat162(__float2bfloat16(l0),
                                               __float2bfloat16(l1));
        hp[i] = *(uint32_t*)&hh;
        lp[i] = *(uint32_t*)&ll;
    }
    *(uint4*)dhi = make_uint4(hp[0], hp[1], hp[2], hp[3]);
    *(uint4*)dlo = make_uint4(lp[0], lp[1], lp[2], lp[3]);
}

__device__ __forceinline__ void pack2(float x, float y,
                                      uint32_t& hi, uint32_t& lo) {
    __nv_bfloat16 hx = __float2bfloat16(x), hy = __float2bfloat16(y);
    float lx = x - __bfloat162float(hx);
    float ly = y - __bfloat162float(hy);
    __nv_bfloat162 h2 = __halves2bfloat162(hx, hy);
    __nv_bfloat162 l2 = __halves2bfloat162(__float2bfloat16(lx),
                                           __float2bfloat16(ly));
    hi = *(uint32_t*)&h2;
    lo = *(uint32_t*)&l2;
}

__global__ __launch_bounds__(256, 1) void flash_hmma(
    const float* __restrict__ Q,
    const float* __restrict__ K,
    const float* __restrict__ V,
    float* __restrict__ O)
{
    extern __shared__ char sf[];
    const uint32_t sb = smem_u32(sf);
    const int tid  = threadIdx.x;
    const int lane = tid & 31;
    const int wid  = tid >> 5;          // 0..7, owns q rows wid*16..+15
    const int grp  = lane >> 2;
    const int tig  = lane & 3;
    const int sub  = lane >> 3;
    const int r8   = lane & 7;

    const int bh = blockIdx.y;
    const int b = bh / HH;
    const int h = bh % HH;
    const int q0 = blockIdx.x * 128;

    const float* Qb = Q + (size_t)b * SS * DM + h * DK;
    const float* Kb = K + (size_t)b * SS * DM + h * DK;
    const float* Vb = V + (size_t)b * SS * DM + h * DK;
    float*       Ob = O + (size_t)b * SS * DM + h * DK;

    // --- load + convert Q (pre-scaled by 1/sqrt(dk)=0.125), hi/lo ---
    {
        const int row  = tid >> 1;
        const int half = tid & 1;
        const float* src = Qb + (size_t)(q0 + row) * DM + half * 32;
        char* qh = sf + FQ_HI + row * RB2 + half * 64;
        char* ql = sf + FQ_LO + row * RB2 + half * 64;
#pragma unroll
        for (int u = 0; u < 4; u++)
            cvt8p(src + u * 8, qh + u * 16, ql + u * 16, 0.125f);
    }
    __syncthreads();

    // --- Q A-fragments (persistent) ---
    uint32_t qhi[4][4], qlo[4][4];
#pragma unroll
    for (int ks = 0; ks < 4; ks++) {
        const uint32_t ro = (uint32_t)((wid * 16 + (sub & 1) * 8 + r8) * RB2
                                       + ks * 32 + (sub >> 1) * 16);
        LDSM4(qhi[ks][0], qhi[ks][1], qhi[ks][2], qhi[ks][3], sb + FQ_HI + ro);
        LDSM4(qlo[ks][0], qlo[ks][1], qlo[ks][2], qlo[ks][3], sb + FQ_LO + ro);
    }

    float m0 = -1e30f, m1 = -1e30f, l0 = 0.0f, l1 = 0.0f;
    float acc[8][4];
#pragma unroll
    for (int nt = 0; nt < 8; nt++)
#pragma unroll
        for (int q = 0; q < 4; q++) acc[nt][q] = 0.0f;

    for (int t = 0; t < SS; t += 64) {
        __syncthreads();   // previous tile's frag reads complete
        // --- convert K,V tile (64 x 64), hi/lo ---
        {
            const int row4 = tid >> 2;      // 0..63
            const int qtr  = tid & 3;       // dk quarter
            const float* ksrc = Kb + (size_t)(t + row4) * DM + qtr * 16;
            const float* vsrc = Vb + (size_t)(t + row4) * DM + qtr * 16;
            char* kh = sf + FK_HI + row4 * RB2 + qtr * 32;
            char* kl = sf + FK_LO + row4 * RB2 + qtr * 32;
            char* vh = sf + FV_HI + row4 * RB2 + qtr * 32;
            char* vl = sf + FV_LO + row4 * RB2 + qtr * 32;
            cvt8p(ksrc,     kh,      kl,      1.0f);
            cvt8p(ksrc + 8, kh + 16, kl + 16, 1.0f);
            cvt8p(vsrc,     vh,      vl,      1.0f);
            cvt8p(vsrc + 8, vh + 16, vl + 16, 1.0f);
        }
        __syncthreads();

        // --- S = Q @ K^T (3-term split) ---
        float s[8][4];
#pragma unroll
        for (int nt = 0; nt < 8; nt++)
#pragma unroll
            for (int q = 0; q < 4; q++) s[nt][q] = 0.0f;

#pragma unroll
        for (int ks = 0; ks < 4; ks++)
#pragma unroll
            for (int np = 0; np < 4; np++) {
                const uint32_t ro =
                    (uint32_t)((np * 16 + (sub >> 1) * 8 + r8) * RB2
                               + ks * 32 + (sub & 1) * 16);
                uint32_t kh4[4], kl4[4];
                LDSM4(kh4[0], kh4[1], kh4[2], kh4[3], sb + FK_HI + ro);
                LDSM4(kl4[0], kl4[1], kl4[2], kl4[3], sb + FK_LO + ro);
                MMA16816(s[2*np],   qhi[ks], kh4[0], kh4[1]);
                MMA16816(s[2*np+1], qhi[ks], kh4[2], kh4[3]);
                MMA16816(s[2*np],   qlo[ks], kh4[0], kh4[1]);
                MMA16816(s[2*np+1], qlo[ks], kh4[2], kh4[3]);
                MMA16816(s[2*np],   qhi[ks], kl4[0], kl4[1]);
                MMA16816(s[2*np+1], qhi[ks], kl4[2], kl4[3]);
            }

        // --- online softmax (rows grp and grp+8; reduce over tig lanes) ---
        float rm0 = -1e30f, rm1 = -1e30f;
#pragma unroll
        for (int nt = 0; nt < 8; nt++) {
            rm0 = fmaxf(rm0, fmaxf(s[nt][0], s[nt][1]));
            rm1 = fmaxf(rm1, fmaxf(s[nt][2], s[nt][3]));
        }
        rm0 = fmaxf(rm0, __shfl_xor_sync(0xffffffffu, rm0, 1));
        rm0 = fmaxf(rm0, __shfl_xor_sync(0xffffffffu, rm0, 2));
        rm1 = fmaxf(rm1, __shfl_xor_sync(0xffffffffu, rm1, 1));
        rm1 = fmaxf(rm1, __shfl_xor_sync(0xffffffffu, rm1, 2));
        const float mn0 = fmaxf(m0, rm0), mn1 = fmaxf(m1, rm1);
        const float f0 = __expf(m0 - mn0), f1 = __expf(m1 - mn1);
        m0 = mn0; m1 = mn1;
        float rs0 = 0.0f, rs1 = 0.0f;
#pragma unroll
        for (int nt = 0; nt < 8; nt++) {
            s[nt][0] = __expf(s[nt][0] - mn0);
            s[nt][1] = __expf(s[nt][1] - mn0);
            s[nt][2] = __expf(s[nt][2] - mn1);
            s[nt][3] = __expf(s[nt][3] - mn1);
            rs0 += s[nt][0] + s[nt][1];
            rs1 += s[nt][2] + s[nt][3];
        }
        rs0 += __shfl_xor_sync(0xffffffffu, rs0, 1);
        rs0 += __shfl_xor_sync(0xffffffffu, rs0, 2);
        rs1 += __shfl_xor_sync(0xffffffffu, rs1, 1);
        rs1 += __shfl_xor_sync(0xffffffffu, rs1, 2);
        l0 = l0 * f0 + rs0;
        l1 = l1 * f1 + rs1;
#pragma unroll
        for (int nt = 0; nt < 8; nt++) {
            acc[nt][0] *= f0; acc[nt][1] *= f0;
            acc[nt][2] *= f1; acc[nt][3] *= f1;
        }

        // --- PV: acc += P @ V (3-term split; P from register repack) ---
#pragma unroll
        for (int ks = 0; ks < 4; ks++) {
            uint32_t phi[4], plo[4];
            pack2(s[2*ks][0],   s[2*ks][1],   phi[0], plo[0]);
            pack2(s[2*ks][2],   s[2*ks][3],   phi[1], plo[1]);
            pack2(s[2*ks+1][0], s[2*ks+1][1], phi[2], plo[2]);
            pack2(s[2*ks+1][2], s[2*ks+1][3], phi[3], plo[3]);
#pragma unroll
            for (int np = 0; np < 4; np++) {
                const uint32_t ro =
                    (uint32_t)((ks * 16 + (sub & 1) * 8 + r8) * RB2
                               + (np * 16 + (sub >> 1) * 8) * 2);
                uint32_t vh4[4], vl4[4];
                LDSM4T(vh4[0], vh4[1], vh4[2], vh4[3], sb + FV_HI + ro);
                LDSM4T(vl4[0], vl4[1], vl4[2], vl4[3], sb + FV_LO + ro);
                MMA16816(acc[2*np],   phi, vh4[0], vh4[1]);
                MMA16816(acc[2*np+1], phi, vh4[2], vh4[3]);
                MMA16816(acc[2*np],   plo, vh4[0], vh4[1]);
                MMA16816(acc[2*np+1], plo, vh4[2], vh4[3]);
                MMA16816(acc[2*np],   phi, vl4[0], vl4[1]);
                MMA16816(acc[2*np+1], phi, vl4[2], vl4[3]);
            }
        }
    }

    // --- epilogue: normalize, write ctx in merged-head layout ---
    const float inv0 = 1.0f / l0, inv1 = 1.0f / l1;
    const int qrow = q0 + wid * 16 + grp;
#pragma unroll
    for (int nt = 0; nt < 8; nt++) {
        const int col = nt * 8 + 2 * tig;
        float2 o0 = make_float2(acc[nt][0] * inv0, acc[nt][1] * inv0);
        float2 o1 = make_float2(acc[nt][2] * inv1, acc[nt][3] * inv1);
        *(float2*)&Ob[(size_t)qrow * DM + col]       = o0;
        *(float2*)&Ob[(size_t)(qrow + 8) * DM + col] = o1;
    }
}

// ===========================================================================
extern "C" void kernel_launch(void* const* d_in, const int* in_sizes, int n_in,
                              void* d_out, int out_size)
{
    const float* query = (const float*)d_in[0];
    const float* key   = (const float*)d_in[1];
    const float* value = (const float*)d_in[2];
    const float* Wq    = (const float*)d_in[3];
    const float* bq    = (const float*)d_in[4];
    const float* Wk    = (const float*)d_in[5];
    const float* bk    = (const float*)d_in[6];
    const float* Wv    = (const float*)d_in[7];
    const float* bv    = (const float*)d_in[8];
    const float* Wo    = (const float*)d_in[9];
    const float* bo    = (const float*)d_in[10];
    float* out = (float*)d_out;

    static float *qp = nullptr, *kp = nullptr, *vp = nullptr, *cp = nullptr;
    static bool init_done = false;
    if (!init_done) {
        cudaGetSymbolAddress((void**)&qp, g_q);
        cudaGetSymbolAddress((void**)&kp, g_k);
        cudaGetSymbolAddress((void**)&vp, g_v);
        cudaGetSymbolAddress((void**)&cp, g_ctx);
        cudaFuncSetAttribute(gemm_hmma,
                             cudaFuncAttributeMaxDynamicSharedMemorySize, GSMEM);
        cudaFuncSetAttribute(flash_hmma,
                             cudaFuncAttributeMaxDynamicSharedMemorySize, FSMEM);
        init_done = true;
    }

    GemmArgs aq{query, Wq, bq, qp};
    GemmArgs ak{key,   Wk, bk, kp};
    GemmArgs av{value, Wv, bv, vp};
    GemmArgs ao{cp,    Wo, bo, out};

    // QKV projections (batched, tensor-core)
    dim3 gqkv(DM / 128, MROWS / 128, 3);     // (6, 32, 3)
    gemm_hmma<<<gqkv, 256, GSMEM>>>(aq, ak, av);

    // Flash attention (tensor-core, hi/lo split)
    dim3 gattn(SS / 128, BB * HH);           // (16, 24)
    flash_hmma<<<gattn, 256, FSMEM>>>(qp, kp, vp, cp);

    // Output projection
    dim3 gout(DM / 128, MROWS / 128, 1);     // (6, 32)
    gemm_hmma<<<gout, 256, GSMEM>>>(ao, ao, ao);
}